// round 1
// baseline (speedup 1.0000x reference)
#include <cuda_runtime.h>
#include <cuda_bf16.h>

// LSTM_24936580121326: 2-layer LSTM (input=1, H=8), B=131072, T=49,
// then relu -> linear(8->1) -> relu on last timestep.
// One thread per batch element; weights broadcast from shared memory.

#define T_STEPS 49

__device__ __forceinline__ float sigf(float x) {
    // 1 / (1 + exp(-x)); __expf = FMUL+MUFU.EX2 (~1e-7 rel err),
    // __fdividef -> MUFU.RCP + MUL.
    float e = __expf(-x);
    return __fdividef(1.0f, 1.0f + e);
}

__device__ __forceinline__ float tanh_fast(float x) {
    // tanh(x) = 1 - 2/(exp(2x)+1); exact limits at +/-inf.
    float e = __expf(2.0f * x);
    return 1.0f - __fdividef(2.0f, 1.0f + e);
}

__global__ void __launch_bounds__(256) lstm_fused_kernel(
    const float* __restrict__ X,
    const float* __restrict__ W_ih0, const float* __restrict__ W_hh0,
    const float* __restrict__ b_ih0, const float* __restrict__ b_hh0,
    const float* __restrict__ W_ih1, const float* __restrict__ W_hh1,
    const float* __restrict__ b_ih1, const float* __restrict__ b_hh1,
    const float* __restrict__ W_lin, const float* __restrict__ b_lin,
    float* __restrict__ out, int Bn)
{
    // ---- stage weights in shared (broadcast-read, float4 rows) ----
    __shared__ float  s_wih0[32];   // layer0 input weights (in=1)
    __shared__ float  s_b0[32];     // b_ih0 + b_hh0
    __shared__ float  s_b1[32];     // b_ih1 + b_hh1
    __shared__ float4 s_whh0[64];   // [32 gates][8] as 2x float4
    __shared__ float4 s_wih1[64];
    __shared__ float4 s_whh1[64];
    __shared__ float  s_wlin[8];
    __shared__ float  s_blin;

    int tid = threadIdx.x;
    if (tid < 32) {
        s_wih0[tid] = W_ih0[tid];
        s_b0[tid]   = b_ih0[tid] + b_hh0[tid];
        s_b1[tid]   = b_ih1[tid] + b_hh1[tid];
    }
    // 256 floats per matrix, 256 threads -> one element each
    if (tid < 256) {
        ((float*)s_whh0)[tid] = W_hh0[tid];
        ((float*)s_wih1)[tid] = W_ih1[tid];
        ((float*)s_whh1)[tid] = W_hh1[tid];
    }
    if (tid < 8)  s_wlin[tid] = W_lin[tid];
    if (tid == 0) s_blin = b_lin[0];
    __syncthreads();

    int b = blockIdx.x * blockDim.x + tid;
    if (b >= Bn) return;

    float h1[8], c1[8], h2[8], c2[8];
#pragma unroll
    for (int u = 0; u < 8; ++u) { h1[u] = 0.f; c1[u] = 0.f; h2[u] = 0.f; c2[u] = 0.f; }

    const float* __restrict__ xp = X + (long long)b * T_STEPS;

    for (int t = 0; t < T_STEPS; ++t) {
        float x = __ldg(xp + t);
        float g[32];

        // ---------- layer 1: gates = W_ih0*x + b + W_hh0 @ h1 ----------
#pragma unroll
        for (int k = 0; k < 32; ++k) {
            float4 wa = s_whh0[2 * k];
            float4 wb = s_whh0[2 * k + 1];
            float a = fmaf(s_wih0[k], x, s_b0[k]);
            a = fmaf(wa.x, h1[0], a);
            a = fmaf(wa.y, h1[1], a);
            a = fmaf(wa.z, h1[2], a);
            a = fmaf(wa.w, h1[3], a);
            a = fmaf(wb.x, h1[4], a);
            a = fmaf(wb.y, h1[5], a);
            a = fmaf(wb.z, h1[6], a);
            a = fmaf(wb.w, h1[7], a);
            g[k] = a;
        }
#pragma unroll
        for (int u = 0; u < 8; ++u) {
            float ig = sigf(g[u]);
            float fg = sigf(g[u + 8]);
            float gg = tanh_fast(g[u + 16]);
            float og = sigf(g[u + 24]);
            c1[u] = fmaf(fg, c1[u], ig * gg);
            h1[u] = og * tanh_fast(c1[u]);
        }

        // ---------- layer 2: gates = W_ih1 @ h1 + b + W_hh1 @ h2 ----------
#pragma unroll
        for (int k = 0; k < 32; ++k) {
            float4 ua = s_wih1[2 * k];
            float4 ub = s_wih1[2 * k + 1];
            float4 va = s_whh1[2 * k];
            float4 vb = s_whh1[2 * k + 1];
            float a = s_b1[k];
            a = fmaf(ua.x, h1[0], a);
            a = fmaf(ua.y, h1[1], a);
            a = fmaf(ua.z, h1[2], a);
            a = fmaf(ua.w, h1[3], a);
            a = fmaf(ub.x, h1[4], a);
            a = fmaf(ub.y, h1[5], a);
            a = fmaf(ub.z, h1[6], a);
            a = fmaf(ub.w, h1[7], a);
            a = fmaf(va.x, h2[0], a);
            a = fmaf(va.y, h2[1], a);
            a = fmaf(va.z, h2[2], a);
            a = fmaf(va.w, h2[3], a);
            a = fmaf(vb.x, h2[4], a);
            a = fmaf(vb.y, h2[5], a);
            a = fmaf(vb.z, h2[6], a);
            a = fmaf(vb.w, h2[7], a);
            g[k] = a;
        }
#pragma unroll
        for (int u = 0; u < 8; ++u) {
            float ig = sigf(g[u]);
            float fg = sigf(g[u + 8]);
            float gg = tanh_fast(g[u + 16]);
            float og = sigf(g[u + 24]);
            c2[u] = fmaf(fg, c2[u], ig * gg);
            h2[u] = og * tanh_fast(c2[u]);
        }
    }

    // ---------- relu -> linear -> relu ----------
    float acc = s_blin;
#pragma unroll
    for (int u = 0; u < 8; ++u)
        acc = fmaf(s_wlin[u], fmaxf(h2[u], 0.0f), acc);
    out[b] = fmaxf(acc, 0.0f);
}

extern "C" void kernel_launch(void* const* d_in, const int* in_sizes, int n_in,
                              void* d_out, int out_size) {
    const float* X     = (const float*)d_in[0];
    const float* W_ih0 = (const float*)d_in[1];
    const float* W_hh0 = (const float*)d_in[2];
    const float* b_ih0 = (const float*)d_in[3];
    const float* b_hh0 = (const float*)d_in[4];
    const float* W_ih1 = (const float*)d_in[5];
    const float* W_hh1 = (const float*)d_in[6];
    const float* b_ih1 = (const float*)d_in[7];
    const float* b_hh1 = (const float*)d_in[8];
    const float* W_lin = (const float*)d_in[9];
    const float* b_lin = (const float*)d_in[10];

    int Bn = out_size;  // one output per batch element
    int threads = 256;
    int blocks = (Bn + threads - 1) / threads;
    lstm_fused_kernel<<<blocks, threads>>>(
        X, W_ih0, W_hh0, b_ih0, b_hh0,
        W_ih1, W_hh1, b_ih1, b_hh1,
        W_lin, b_lin, (float*)d_out, Bn);
}